// round 4
// baseline (speedup 1.0000x reference)
#include <cuda_runtime.h>
#include <cuda_bf16.h>

#define G      8
#define L      64
#define CCH    512
#define NB     32
#define HWSZ   3136
#define MTOT   (NB*HWSZ)
#define EPSV   1e-4f
#define NPI    19
#define SPLITS 2
#define SCOLS  (HWSZ/SPLITS)   // 1568 = 49*32
#define NCHK   (NB*SPLITS)     // 64 partial chunks per group
#define TT     32

// ---------------- static scratch ----------------
__device__ float g_pg  [(size_t)G*NCHK*L*L];
__device__ float g_psum[(size_t)G*NCHK*L];
__device__ float g_cov [(size_t)G*L*L];
__device__ float g_mu  [CCH];
__device__ float g_R   [(size_t)CCH*L];
__device__ float g_off [CCH];

// ---------------- packed f32x2 helpers ----------------
typedef unsigned long long ull;
__device__ __forceinline__ ull pack2(float lo, float hi){
    ull r; asm("mov.b64 %0,{%1,%2};" : "=l"(r) : "f"(lo), "f"(hi)); return r;
}
__device__ __forceinline__ void fma2(ull& d, ull a, ull b){
    asm("fma.rn.f32x2 %0,%1,%2,%0;" : "+l"(d) : "l"(a), "l"(b));
}
__device__ __forceinline__ float2 unpk(ull v){
    float a, b; asm("mov.b64 {%0,%1},%2;" : "=f"(a), "=f"(b) : "l"(v));
    return make_float2(a, b);
}

// =====================================================================
// Kernel 1: fused channel-sum + Gram partials.
// grid (SPLITS, NB, G), 128 threads. Transposed tile: tileT[cc][row].
// Thread (ti=tid>>4, tj=tid&15): 8 rows (pairs) x 4 cols of Gram.
// =====================================================================
__global__ __launch_bounds__(128) void zca_gram(const float* __restrict__ x)
{
    const int g = blockIdx.z, n = blockIdx.y, sp = blockIdx.x;
    const float* xb = x + ((size_t)n*CCH + (size_t)g*L)*HWSZ + (size_t)sp*SCOLS;

    __shared__ float tileT[TT][L+2];   // [col][row], stride 66
    __shared__ float rs_s[L][8];

    const int tid  = threadIdx.x;
    const int ti   = tid >> 4, tj = tid & 15;
    const int i0   = ti*8,     j0 = tj*4;
    const int rrow = tid >> 3, rcol = tid & 7;

    ull acc[4][4];
    #pragma unroll
    for (int r = 0; r < 4; ++r)
        #pragma unroll
        for (int c = 0; c < 4; ++c) acc[r][c] = 0ull;

    float rsum[4] = {0.f,0.f,0.f,0.f};

    for (int s = 0; s < SCOLS; s += TT) {
        __syncthreads();
        #pragma unroll
        for (int kk = 0; kk < 4; ++kk) {
            const int row = rrow + 16*kk;
            const float4 v = *(const float4*)(xb + (size_t)row*HWSZ + s + rcol*4);
            tileT[rcol*4+0][row] = v.x; tileT[rcol*4+1][row] = v.y;
            tileT[rcol*4+2][row] = v.z; tileT[rcol*4+3][row] = v.w;
            rsum[kk] += (v.x + v.y) + (v.z + v.w);
        }
        __syncthreads();

        #pragma unroll 8
        for (int cc = 0; cc < TT; ++cc) {
            ull a2[4]; ull bb[4];
            #pragma unroll
            for (int r = 0; r < 4; ++r) a2[r] = *(const ull*)&tileT[cc][i0 + 2*r];
            #pragma unroll
            for (int c = 0; c < 4; ++c) { float b = tileT[cc][j0 + c]; bb[c] = pack2(b, b); }
            #pragma unroll
            for (int r = 0; r < 4; ++r)
                #pragma unroll
                for (int c = 0; c < 4; ++c) fma2(acc[r][c], a2[r], bb[c]);
        }
    }

    const int ch = n*SPLITS + sp;
    float* pg = g_pg + (size_t)(g*NCHK + ch)*L*L;
    #pragma unroll
    for (int r = 0; r < 4; ++r)
        #pragma unroll
        for (int c = 0; c < 4; ++c) {
            float2 f = unpk(acc[r][c]);
            pg[(i0+2*r  )*L + j0 + c] = f.x;
            pg[(i0+2*r+1)*L + j0 + c] = f.y;
        }

    __syncthreads();
    #pragma unroll
    for (int kk = 0; kk < 4; ++kk) rs_s[rrow + 16*kk][rcol] = rsum[kk];
    __syncthreads();
    if (tid < L) {
        float s = 0.f;
        #pragma unroll
        for (int q = 0; q < 8; ++q) s += rs_s[tid][q];
        g_psum[(g*NCHK + ch)*L + tid] = s;
    }
}

// =====================================================================
// Kernel 2: reduce partials -> mu, cov = Gram/M - mu mu^T + eps I
// =====================================================================
__global__ __launch_bounds__(256) void zca_finalize()
{
    const int g = blockIdx.x, tid = threadIdx.x;
    __shared__ float mu_s[L];
    if (tid < L) {
        float s0=0.f,s1=0.f,s2=0.f,s3=0.f;
        for (int ch = 0; ch < NCHK; ch += 4) {
            s0 += g_psum[(g*NCHK + ch  )*L + tid];
            s1 += g_psum[(g*NCHK + ch+1)*L + tid];
            s2 += g_psum[(g*NCHK + ch+2)*L + tid];
            s3 += g_psum[(g*NCHK + ch+3)*L + tid];
        }
        const float m = ((s0+s1)+(s2+s3)) / (float)MTOT;
        mu_s[tid] = m;
        g_mu[g*L + tid] = m;
    }
    __syncthreads();
    float acc[16];
    #pragma unroll
    for (int e = 0; e < 16; ++e) acc[e] = 0.f;
    for (int ch = 0; ch < NCHK; ++ch) {
        const float* p = g_pg + (size_t)(g*NCHK + ch)*L*L;
        #pragma unroll
        for (int e = 0; e < 16; ++e) acc[e] += p[tid + e*256];
    }
    #pragma unroll
    for (int e = 0; e < 16; ++e) {
        const int idx = tid + e*256, i = idx >> 6, j = idx & 63;
        float c = acc[e] / (float)MTOT - mu_s[i]*mu_s[j];
        if (i == j) c += EPSV;
        g_cov[g*L*L + idx] = c;
    }
}

// =====================================================================
// Kernel 3: sequential power iteration + deflation. grid G, 64 threads.
// =====================================================================
__device__ __forceinline__ float dot64(const float* a, const float* v){
    float s0=0.f,s1=0.f,s2=0.f,s3=0.f;
    #pragma unroll
    for (int k = 0; k < L; k += 4) {
        s0 = fmaf(a[k  ], v[k  ], s0);
        s1 = fmaf(a[k+1], v[k+1], s1);
        s2 = fmaf(a[k+2], v[k+2], s2);
        s3 = fmaf(a[k+3], v[k+3], s3);
    }
    return (s0+s1)+(s2+s3);
}

__device__ __forceinline__ float blkred(float r, volatile float* buf2, int tid){
    #pragma unroll
    for (int m = 16; m; m >>= 1) r += __shfl_xor_sync(0xffffffffu, r, m);
    __syncthreads();
    if ((tid & 31) == 0) buf2[tid >> 5] = r;
    __syncthreads();
    return buf2[0] + buf2[1];
}

__global__ __launch_bounds__(64) void zca_eigen(const float* __restrict__ v_init,
                                               const float* __restrict__ weight,
                                               const float* __restrict__ bias)
{
    const int g = blockIdx.x, i = threadIdx.x;
    __shared__ float vb[2][L];
    __shared__ float red2[2];

    float a[L], S[L];
    #pragma unroll
    for (int k = 0; k < L; ++k) { a[k] = g_cov[(size_t)g*L*L + i*L + k]; S[k] = 0.f; }

    float lam_prev = 0.f;

    for (int j = 0; j < L; ++j) {
        vb[0][i] = v_init[(size_t)(g*L + j)*L + i];
        __syncthreads();
        int p = 0;
        float w = 0.f;
        #pragma unroll 1
        for (int it = 0; it < NPI; ++it) {
            w = dot64(a, vb[p]);
            vb[p^1][i] = w;
            __syncthreads();
            p ^= 1;
        }
        const float n2  = blkred(w*w, red2, i);
        const float vh  = w * (1.0f / (sqrtf(n2) + 1e-12f));
        vb[p^1][i] = vh;
        __syncthreads();
        const float* cv = vb[p^1];
        const float av  = dot64(a, cv);
        const float num = blkred(vh*av, red2, i);
        const float den = blkred(vh*vh, red2, i);
        const float lam = num / den;
        if (j > 0 && (lam_prev < lam || lam < EPSV)) break;
        const float c1 = rsqrtf(lam) * vh;
        #pragma unroll
        for (int k = 0; k < L; ++k) {
            const float t = cv[k];
            S[k] = fmaf(c1, t, S[k]);
            a[k] = fmaf(-av, t, a[k]);
        }
        lam_prev = lam;
        __syncthreads();
    }

    // fold affine: R = diag(w) S, off = bias - R mu
    const int c = g*L + i;
    const float wgt = weight[c];
    float dm = 0.f;
    #pragma unroll
    for (int k = 0; k < L; ++k) dm = fmaf(S[k], g_mu[g*L + k], dm);
    g_off[c] = bias[c] - wgt*dm;
    #pragma unroll
    for (int k = 0; k < L; ++k) g_R[(size_t)c*L + k] = wgt * S[k];
}

// =====================================================================
// Kernel 4: whiten + affine: out = R x + off.
// grid (7, NB, G), 128 threads; 7 inner tiles of 64 cols each.
// =====================================================================
#define WTIL 64
__global__ __launch_bounds__(128) void zca_whiten(const float* __restrict__ x,
                                                  float* __restrict__ out)
{
    const int bx = blockIdx.x, n = blockIdx.y, g = blockIdx.z;
    __shared__ float R_sT[L][L+4];     // [k][i], stride 68 (16B aligned)
    __shared__ float tile[L][WTIL+4];  // [k][col], stride 68
    __shared__ float off_s[L];

    const int tid = threadIdx.x;
    const int ti  = tid >> 4, tj = tid & 15;
    const int i0  = ti*8,     j0 = tj*4;
    const int lrow = tid >> 1, lc = (tid & 1)*32;

    {   // load R transposed
        const int row = tid >> 1, kh = (tid & 1)*32;
        #pragma unroll
        for (int q = 0; q < 8; ++q) {
            const float4 rv = *(const float4*)&g_R[(size_t)(g*L + row)*L + kh + 4*q];
            R_sT[kh+4*q+0][row] = rv.x; R_sT[kh+4*q+1][row] = rv.y;
            R_sT[kh+4*q+2][row] = rv.z; R_sT[kh+4*q+3][row] = rv.w;
        }
        if (tid < L) off_s[tid] = g_off[g*L + tid];
    }

    const float* xb = x + ((size_t)n*CCH + (size_t)g*L)*HWSZ;
    float*       ob = out + ((size_t)n*CCH + (size_t)g*L)*HWSZ;

    for (int t = 0; t < 7; ++t) {
        const int colbase = bx*448 + t*WTIL;
        __syncthreads();   // WAR on tile (and first-iter R ready)
        #pragma unroll
        for (int q = 0; q < 8; ++q) {
            const float4 v = *(const float4*)(xb + (size_t)lrow*HWSZ + colbase + lc + 4*q);
            *(float4*)&tile[lrow][lc + 4*q] = v;
        }
        __syncthreads();

        ull acc[8][2];
        #pragma unroll
        for (int r = 0; r < 8; ++r) { acc[r][0] = 0ull; acc[r][1] = 0ull; }

        #pragma unroll 8
        for (int k = 0; k < L; ++k) {
            const float4 A1 = *(const float4*)&R_sT[k][i0];
            const float4 A2 = *(const float4*)&R_sT[k][i0+4];
            const ull b0 = *(const ull*)&tile[k][j0];
            const ull b1 = *(const ull*)&tile[k][j0+2];
            ull ar[8];
            ar[0]=pack2(A1.x,A1.x); ar[1]=pack2(A1.y,A1.y);
            ar[2]=pack2(A1.z,A1.z); ar[3]=pack2(A1.w,A1.w);
            ar[4]=pack2(A2.x,A2.x); ar[5]=pack2(A2.y,A2.y);
            ar[6]=pack2(A2.z,A2.z); ar[7]=pack2(A2.w,A2.w);
            #pragma unroll
            for (int r = 0; r < 8; ++r) { fma2(acc[r][0], ar[r], b0); fma2(acc[r][1], ar[r], b1); }
        }

        #pragma unroll
        for (int r = 0; r < 8; ++r) {
            const float o = off_s[i0 + r];
            const float2 u = unpk(acc[r][0]), v = unpk(acc[r][1]);
            float4 res; res.x = u.x+o; res.y = u.y+o; res.z = v.x+o; res.w = v.y+o;
            *(float4*)(ob + (size_t)(i0 + r)*HWSZ + colbase + j0) = res;
        }
    }
}

// =====================================================================
extern "C" void kernel_launch(void* const* d_in, const int* in_sizes, int n_in,
                              void* d_out, int out_size)
{
    const float* x      = (const float*)d_in[0];
    const float* v_init = (const float*)d_in[1];
    const float* weight = (const float*)d_in[2];
    const float* bias   = (const float*)d_in[3];
    float* out = (float*)d_out;
    (void)in_sizes; (void)n_in; (void)out_size;

    zca_gram    <<<dim3(SPLITS, NB, G), 128>>>(x);
    zca_finalize<<<G, 256>>>();
    zca_eigen   <<<G, 64>>>(v_init, weight, bias);
    zca_whiten  <<<dim3(7, NB, G), 128>>>(x, out);
}

// round 9
// speedup vs baseline: 1.0710x; 1.0710x over previous
#include <cuda_runtime.h>

#define G      8
#define L      64
#define CCH    512
#define NB     32
#define HWSZ   3136
#define MTOT   (NB*HWSZ)
#define EPSV   1e-4f
#define NPI    19
#define SPLITS 2
#define SCOLS  (HWSZ/SPLITS)   // 1568
#define NCHK   (NB*SPLITS)     // 64 partial chunks per group
#define TT     32

// ---------------- static scratch ----------------
__device__ float g_pg  [(size_t)G*NCHK*L*L];   // 8.4 MB
__device__ float g_psum[(size_t)G*NCHK*L];
__device__ float g_cov [(size_t)G*L*L];
__device__ float g_mu  [CCH];
__device__ float g_R   [(size_t)CCH*L];
__device__ float g_off [CCH];

// ---------------- packed f32x2 helpers ----------------
typedef unsigned long long ull;
__device__ __forceinline__ ull pack2(float lo, float hi){
    ull r; asm("mov.b64 %0,{%1,%2};" : "=l"(r) : "f"(lo), "f"(hi)); return r;
}
__device__ __forceinline__ void fma2(ull& d, ull a, ull b){
    asm("fma.rn.f32x2 %0,%1,%2,%0;" : "+l"(d) : "l"(a), "l"(b));
}
__device__ __forceinline__ float2 unpk(ull v){
    float a, b; asm("mov.b64 {%0,%1},%2;" : "=f"(a), "=f"(b) : "l"(v));
    return make_float2(a, b);
}

// =====================================================================
// Kernel 1: fused channel-sum + Gram partials.
// grid (SPLITS, NB, G), 64 threads, 8x8 output tile per thread.
// Per-element accumulation order identical to the R4 passing run:
// one f32x2 lane per Gram element, cc ascending per tile, s ascending;
// rsum per-(row, 4-col-chunk) over s ascending, chunks summed ascending.
// =====================================================================
__global__ __launch_bounds__(64) void zca_gram(const float* __restrict__ x)
{
    const int g = blockIdx.z, n = blockIdx.y, sp = blockIdx.x;
    const float* xb = x + ((size_t)n*CCH + (size_t)g*L)*HWSZ + (size_t)sp*SCOLS;

    __shared__ float tileT[TT][L+4];   // [col][row], stride 68 (16B-aligned rows)
    __shared__ float outb[L*L];
    __shared__ float rs_s[L][8];

    const int tid = threadIdx.x;
    const int ti  = tid >> 3, tj = tid & 7;
    const int i0  = ti*8,     j0 = tj*8;

    ull acc[4][8];
    #pragma unroll
    for (int r = 0; r < 4; ++r)
        #pragma unroll
        for (int c = 0; c < 8; ++c) acc[r][c] = 0ull;
    float rsum[8] = {0.f,0.f,0.f,0.f,0.f,0.f,0.f,0.f};

    for (int s = 0; s < SCOLS; s += TT) {
        __syncthreads();   // WAR on tileT
        #pragma unroll
        for (int q = 0; q < 8; ++q) {
            const int row = ti + 8*q;
            const float4 v = *(const float4*)(xb + (size_t)row*HWSZ + s + tj*4);
            tileT[tj*4+0][row] = v.x; tileT[tj*4+1][row] = v.y;
            tileT[tj*4+2][row] = v.z; tileT[tj*4+3][row] = v.w;
            rsum[q] += (v.x + v.y) + (v.z + v.w);
        }
        __syncthreads();

        #pragma unroll 8
        for (int cc = 0; cc < TT; ++cc) {
            ull a2[4];
            #pragma unroll
            for (int r = 0; r < 4; ++r) a2[r] = *(const ull*)&tileT[cc][i0 + 2*r];
            const float4 B1 = *(const float4*)&tileT[cc][j0];
            const float4 B2 = *(const float4*)&tileT[cc][j0+4];
            ull bp[8];
            bp[0]=pack2(B1.x,B1.x); bp[1]=pack2(B1.y,B1.y);
            bp[2]=pack2(B1.z,B1.z); bp[3]=pack2(B1.w,B1.w);
            bp[4]=pack2(B2.x,B2.x); bp[5]=pack2(B2.y,B2.y);
            bp[6]=pack2(B2.z,B2.z); bp[7]=pack2(B2.w,B2.w);
            #pragma unroll
            for (int r = 0; r < 4; ++r)
                #pragma unroll
                for (int c = 0; c < 8; ++c) fma2(acc[r][c], a2[r], bp[c]);
        }
    }

    // stage results in smem, then coalesced writes
    #pragma unroll
    for (int r = 0; r < 4; ++r)
        #pragma unroll
        for (int c = 0; c < 8; ++c) {
            const float2 f = unpk(acc[r][c]);
            outb[(i0+2*r  )*L + j0 + c] = f.x;
            outb[(i0+2*r+1)*L + j0 + c] = f.y;
        }
    #pragma unroll
    for (int q = 0; q < 8; ++q) rs_s[ti + 8*q][tj] = rsum[q];
    __syncthreads();

    const int ch = n*SPLITS + sp;
    float* pg = g_pg + (size_t)(g*NCHK + ch)*L*L;
    #pragma unroll
    for (int q = 0; q < 16; ++q)
        *(float4*)&pg[(tid + 64*q)*4] = *(const float4*)&outb[(tid + 64*q)*4];
    {
        float ssum = 0.f;
        #pragma unroll
        for (int q = 0; q < 8; ++q) ssum += rs_s[tid][q];
        g_psum[(g*NCHK + ch)*L + tid] = ssum;
    }
}

// =====================================================================
// Kernel 2: reduce partials -> mu, cov = Gram/M - mu mu^T + eps I
// grid (4, G), 256 threads. Per-element ch-order identical to R4.
// =====================================================================
__global__ __launch_bounds__(256) void zca_finalize()
{
    const int part = blockIdx.x, g = blockIdx.y, tid = threadIdx.x;
    __shared__ float mu_s[L];
    if (tid < L) {
        float s0=0.f,s1=0.f,s2=0.f,s3=0.f;
        for (int ch = 0; ch < NCHK; ch += 4) {
            s0 += g_psum[(g*NCHK + ch  )*L + tid];
            s1 += g_psum[(g*NCHK + ch+1)*L + tid];
            s2 += g_psum[(g*NCHK + ch+2)*L + tid];
            s3 += g_psum[(g*NCHK + ch+3)*L + tid];
        }
        const float m = ((s0+s1)+(s2+s3)) / (float)MTOT;
        mu_s[tid] = m;
        if (part == 0) g_mu[g*L + tid] = m;
    }
    __syncthreads();
    const int base = part*1024;
    float acc[4] = {0.f,0.f,0.f,0.f};
    for (int ch = 0; ch < NCHK; ++ch) {
        const float* p = g_pg + (size_t)(g*NCHK + ch)*L*L + base;
        #pragma unroll
        for (int e = 0; e < 4; ++e) acc[e] += p[tid + e*256];
    }
    #pragma unroll
    for (int e = 0; e < 4; ++e) {
        const int idx = base + tid + e*256, i = idx >> 6, j = idx & 63;
        float c = acc[e] / (float)MTOT - mu_s[i]*mu_s[j];
        if (i == j) c += EPSV;
        g_cov[g*L*L + idx] = c;
    }
}

// =====================================================================
// Kernel 3: sequential power iteration + deflation. grid G, 64 threads.
// TRUE verbatim R4 arithmetic, including c1 = rsqrtf(lam) * vh (the
// outer-product row factor that R5/R7 dropped — the 8.007714 bug).
// =====================================================================
__device__ __forceinline__ float dot64(const float* a, const float* v){
    float s0=0.f,s1=0.f,s2=0.f,s3=0.f;
    #pragma unroll
    for (int k = 0; k < L; k += 4) {
        s0 = fmaf(a[k  ], v[k  ], s0);
        s1 = fmaf(a[k+1], v[k+1], s1);
        s2 = fmaf(a[k+2], v[k+2], s2);
        s3 = fmaf(a[k+3], v[k+3], s3);
    }
    return (s0+s1)+(s2+s3);
}

__device__ __forceinline__ float blkred(float r, volatile float* buf2, int tid){
    #pragma unroll
    for (int m = 16; m; m >>= 1) r += __shfl_xor_sync(0xffffffffu, r, m);
    __syncthreads();
    if ((tid & 31) == 0) buf2[tid >> 5] = r;
    __syncthreads();
    return buf2[0] + buf2[1];
}

__global__ __launch_bounds__(64) void zca_eigen(const float* __restrict__ v_init,
                                               const float* __restrict__ weight,
                                               const float* __restrict__ bias)
{
    const int g = blockIdx.x, i = threadIdx.x;
    __shared__ float vb[2][L];
    __shared__ float red2[2];

    float a[L], S[L];
    #pragma unroll
    for (int k = 0; k < L; ++k) { a[k] = g_cov[(size_t)g*L*L + i*L + k]; S[k] = 0.f; }

    float lam_prev = 0.f;

    for (int j = 0; j < L; ++j) {
        vb[0][i] = v_init[(size_t)(g*L + j)*L + i];
        __syncthreads();
        int p = 0;
        float w = 0.f;
        #pragma unroll 1
        for (int it = 0; it < NPI; ++it) {
            w = dot64(a, vb[p]);
            vb[p^1][i] = w;
            __syncthreads();
            p ^= 1;
        }
        const float n2  = blkred(w*w, red2, i);
        const float vh  = w * (1.0f / (sqrtf(n2) + 1e-12f));
        vb[p^1][i] = vh;
        __syncthreads();
        const float* cv = vb[p^1];
        const float av  = dot64(a, cv);
        const float num = blkred(vh*av, red2, i);
        const float den = blkred(vh*vh, red2, i);
        const float lam = num / den;
        if (j > 0 && (lam_prev < lam || lam < EPSV)) break;
        const float c1 = rsqrtf(lam) * vh;   // row factor vh: S += rsqrt(lam) * v v^T
        #pragma unroll
        for (int k = 0; k < L; ++k) {
            const float t = cv[k];
            S[k] = fmaf(c1, t, S[k]);
            a[k] = fmaf(-av, t, a[k]);
        }
        lam_prev = lam;
        __syncthreads();
    }

    // fold affine: R = diag(w) S, off = bias - R mu
    const int c = g*L + i;
    const float wgt = weight[c];
    float dm = 0.f;
    #pragma unroll
    for (int k = 0; k < L; ++k) dm = fmaf(S[k], g_mu[g*L + k], dm);
    g_off[c] = bias[c] - wgt*dm;
    #pragma unroll
    for (int k = 0; k < L; ++k) g_R[(size_t)c*L + k] = wgt * S[k];
}

// =====================================================================
// Kernel 4: whiten + affine: out = R x + off.
// grid (49, NB/2, G), 128 threads: two n-batches per block share R^T.
// Each of the 64 threads per half computes an 8x8 output tile.
// smem = 16KB (R^T) + 32KB (two 64x64 x tiles) = 48KB.
// =====================================================================
__global__ __launch_bounds__(128) void zca_whiten(const float* __restrict__ x,
                                                  float* __restrict__ out)
{
    const int bx = blockIdx.x, g = blockIdx.z;
    __shared__ float R_sT[L][L];       // [k][i]
    __shared__ float tile[2][L][L];    // [half][k][col]

    const int tid  = threadIdx.x;
    const int half = tid >> 6, t64 = tid & 63;
    const int ti   = t64 >> 3, tj = t64 & 7;
    const int i0   = ti*8,     j0 = tj*8;
    const int n    = blockIdx.y*2 + half;

    {   // load R transposed (both halves cooperate)
        const int row = tid >> 1, kh = (tid & 1)*32;
        #pragma unroll
        for (int q = 0; q < 8; ++q) {
            const float4 rv = *(const float4*)&g_R[(size_t)(g*L + row)*L + kh + 4*q];
            R_sT[kh+4*q+0][row] = rv.x; R_sT[kh+4*q+1][row] = rv.y;
            R_sT[kh+4*q+2][row] = rv.z; R_sT[kh+4*q+3][row] = rv.w;
        }
    }

    const int colbase = bx * 64;
    const float* xb = x   + ((size_t)n*CCH + (size_t)g*L)*HWSZ + colbase;
    float*       ob = out + ((size_t)n*CCH + (size_t)g*L)*HWSZ + colbase;

    #pragma unroll
    for (int q = 0; q < 16; ++q) {
        const int row = (t64 >> 4) + 4*q;
        const int c4  = (t64 & 15)*4;
        *(float4*)&tile[half][row][c4] = *(const float4*)(xb + (size_t)row*HWSZ + c4);
    }
    __syncthreads();

    ull acc[8][4];
    #pragma unroll
    for (int r = 0; r < 8; ++r)
        #pragma unroll
        for (int c = 0; c < 4; ++c) acc[r][c] = 0ull;

    #pragma unroll 8
    for (int k = 0; k < L; ++k) {
        const float4 A1 = *(const float4*)&R_sT[k][i0];
        const float4 A2 = *(const float4*)&R_sT[k][i0+4];
        const float4 B1 = *(const float4*)&tile[half][k][j0];
        const float4 B2 = *(const float4*)&tile[half][k][j0+4];
        const ull b0 = pack2(B1.x,B1.y), b1 = pack2(B1.z,B1.w);
        const ull b2 = pack2(B2.x,B2.y), b3 = pack2(B2.z,B2.w);
        ull ar[8];
        ar[0]=pack2(A1.x,A1.x); ar[1]=pack2(A1.y,A1.y);
        ar[2]=pack2(A1.z,A1.z); ar[3]=pack2(A1.w,A1.w);
        ar[4]=pack2(A2.x,A2.x); ar[5]=pack2(A2.y,A2.y);
        ar[6]=pack2(A2.z,A2.z); ar[7]=pack2(A2.w,A2.w);
        #pragma unroll
        for (int r = 0; r < 8; ++r) {
            fma2(acc[r][0], ar[r], b0); fma2(acc[r][1], ar[r], b1);
            fma2(acc[r][2], ar[r], b2); fma2(acc[r][3], ar[r], b3);
        }
    }

    #pragma unroll
    for (int r = 0; r < 8; ++r) {
        const float o = g_off[g*L + i0 + r];   // L2-cached broadcast
        const float2 u0=unpk(acc[r][0]), u1=unpk(acc[r][1]);
        const float2 u2=unpk(acc[r][2]), u3=unpk(acc[r][3]);
        float4 w0, w1;
        w0.x=u0.x+o; w0.y=u0.y+o; w0.z=u1.x+o; w0.w=u1.y+o;
        w1.x=u2.x+o; w1.y=u2.y+o; w1.z=u3.x+o; w1.w=u3.y+o;
        *(float4*)(ob + (size_t)(i0+r)*HWSZ + j0    ) = w0;
        *(float4*)(ob + (size_t)(i0+r)*HWSZ + j0 + 4) = w1;
    }
}

// =====================================================================
extern "C" void kernel_launch(void* const* d_in, const int* in_sizes, int n_in,
                              void* d_out, int out_size)
{
    const float* x      = (const float*)d_in[0];
    const float* v_init = (const float*)d_in[1];
    const float* weight = (const float*)d_in[2];
    const float* bias   = (const float*)d_in[3];
    float* out = (float*)d_out;
    (void)in_sizes; (void)n_in; (void)out_size;

    zca_gram    <<<dim3(SPLITS, NB, G), 64>>>(x);
    zca_finalize<<<dim3(4, G), 256>>>();
    zca_eigen   <<<G, 64>>>(v_init, weight, bias);
    zca_whiten  <<<dim3(49, NB/2, G), 128>>>(x, out);
}

// round 10
// speedup vs baseline: 1.1346x; 1.0594x over previous
#include <cuda_runtime.h>

#define G      8
#define L      64
#define CCH    512
#define NB     32
#define HWSZ   3136
#define MTOT   (NB*HWSZ)
#define EPSV   1e-4f
#define NPI    19
#define SPLITS 2
#define SCOLS  (HWSZ/SPLITS)   // 1568
#define NCHK   (NB*SPLITS)     // 64 partial chunks per group
#define TT     32

// ---------------- static scratch ----------------
__device__ float g_pg  [(size_t)G*NCHK*L*L];   // 8.4 MB
__device__ float g_psum[(size_t)G*NCHK*L];
__device__ float g_cov [(size_t)G*L*L];
__device__ float g_mu  [CCH];
__device__ float g_R   [(size_t)CCH*L];
__device__ float g_off [CCH];

// ---------------- packed f32x2 helpers ----------------
typedef unsigned long long ull;
__device__ __forceinline__ ull pack2(float lo, float hi){
    ull r; asm("mov.b64 %0,{%1,%2};" : "=l"(r) : "f"(lo), "f"(hi)); return r;
}
__device__ __forceinline__ void fma2(ull& d, ull a, ull b){
    asm("fma.rn.f32x2 %0,%1,%2,%0;" : "+l"(d) : "l"(a), "l"(b));
}
__device__ __forceinline__ float2 unpk(ull v){
    float a, b; asm("mov.b64 {%0,%1},%2;" : "=f"(a), "=f"(b) : "l"(v));
    return make_float2(a, b);
}

// =====================================================================
// Kernel 1: fused channel-sum + Gram partials. (byte-identical to R8)
// =====================================================================
__global__ __launch_bounds__(64) void zca_gram(const float* __restrict__ x)
{
    const int g = blockIdx.z, n = blockIdx.y, sp = blockIdx.x;
    const float* xb = x + ((size_t)n*CCH + (size_t)g*L)*HWSZ + (size_t)sp*SCOLS;

    __shared__ float tileT[TT][L+4];   // [col][row], stride 68 (16B-aligned rows)
    __shared__ float outb[L*L];
    __shared__ float rs_s[L][8];

    const int tid = threadIdx.x;
    const int ti  = tid >> 3, tj = tid & 7;
    const int i0  = ti*8,     j0 = tj*8;

    ull acc[4][8];
    #pragma unroll
    for (int r = 0; r < 4; ++r)
        #pragma unroll
        for (int c = 0; c < 8; ++c) acc[r][c] = 0ull;
    float rsum[8] = {0.f,0.f,0.f,0.f,0.f,0.f,0.f,0.f};

    for (int s = 0; s < SCOLS; s += TT) {
        __syncthreads();   // WAR on tileT
        #pragma unroll
        for (int q = 0; q < 8; ++q) {
            const int row = ti + 8*q;
            const float4 v = *(const float4*)(xb + (size_t)row*HWSZ + s + tj*4);
            tileT[tj*4+0][row] = v.x; tileT[tj*4+1][row] = v.y;
            tileT[tj*4+2][row] = v.z; tileT[tj*4+3][row] = v.w;
            rsum[q] += (v.x + v.y) + (v.z + v.w);
        }
        __syncthreads();

        #pragma unroll 8
        for (int cc = 0; cc < TT; ++cc) {
            ull a2[4];
            #pragma unroll
            for (int r = 0; r < 4; ++r) a2[r] = *(const ull*)&tileT[cc][i0 + 2*r];
            const float4 B1 = *(const float4*)&tileT[cc][j0];
            const float4 B2 = *(const float4*)&tileT[cc][j0+4];
            ull bp[8];
            bp[0]=pack2(B1.x,B1.x); bp[1]=pack2(B1.y,B1.y);
            bp[2]=pack2(B1.z,B1.z); bp[3]=pack2(B1.w,B1.w);
            bp[4]=pack2(B2.x,B2.x); bp[5]=pack2(B2.y,B2.y);
            bp[6]=pack2(B2.z,B2.z); bp[7]=pack2(B2.w,B2.w);
            #pragma unroll
            for (int r = 0; r < 4; ++r)
                #pragma unroll
                for (int c = 0; c < 8; ++c) fma2(acc[r][c], a2[r], bp[c]);
        }
    }

    #pragma unroll
    for (int r = 0; r < 4; ++r)
        #pragma unroll
        for (int c = 0; c < 8; ++c) {
            const float2 f = unpk(acc[r][c]);
            outb[(i0+2*r  )*L + j0 + c] = f.x;
            outb[(i0+2*r+1)*L + j0 + c] = f.y;
        }
    #pragma unroll
    for (int q = 0; q < 8; ++q) rs_s[ti + 8*q][tj] = rsum[q];
    __syncthreads();

    const int ch = n*SPLITS + sp;
    float* pg = g_pg + (size_t)(g*NCHK + ch)*L*L;
    #pragma unroll
    for (int q = 0; q < 16; ++q)
        *(float4*)&pg[(tid + 64*q)*4] = *(const float4*)&outb[(tid + 64*q)*4];
    {
        float ssum = 0.f;
        #pragma unroll
        for (int q = 0; q < 8; ++q) ssum += rs_s[tid][q];
        g_psum[(g*NCHK + ch)*L + tid] = ssum;
    }
}

// =====================================================================
// Kernel 2: reduce partials -> mu, cov. (byte-identical to R8)
// =====================================================================
__global__ __launch_bounds__(256) void zca_finalize()
{
    const int part = blockIdx.x, g = blockIdx.y, tid = threadIdx.x;
    __shared__ float mu_s[L];
    if (tid < L) {
        float s0=0.f,s1=0.f,s2=0.f,s3=0.f;
        for (int ch = 0; ch < NCHK; ch += 4) {
            s0 += g_psum[(g*NCHK + ch  )*L + tid];
            s1 += g_psum[(g*NCHK + ch+1)*L + tid];
            s2 += g_psum[(g*NCHK + ch+2)*L + tid];
            s3 += g_psum[(g*NCHK + ch+3)*L + tid];
        }
        const float m = ((s0+s1)+(s2+s3)) / (float)MTOT;
        mu_s[tid] = m;
        if (part == 0) g_mu[g*L + tid] = m;
    }
    __syncthreads();
    const int base = part*1024;
    float acc[4] = {0.f,0.f,0.f,0.f};
    for (int ch = 0; ch < NCHK; ++ch) {
        const float* p = g_pg + (size_t)(g*NCHK + ch)*L*L + base;
        #pragma unroll
        for (int e = 0; e < 4; ++e) acc[e] += p[tid + e*256];
    }
    #pragma unroll
    for (int e = 0; e < 4; ++e) {
        const int idx = base + tid + e*256, i = idx >> 6, j = idx & 63;
        float c = acc[e] / (float)MTOT - mu_s[i]*mu_s[j];
        if (i == j) c += EPSV;
        g_cov[g*L*L + idx] = c;
    }
}

// =====================================================================
// Kernel 3: eigen. (byte-identical to R8, incl. c1 = rsqrtf(lam)*vh)
// =====================================================================
__device__ __forceinline__ float dot64(const float* a, const float* v){
    float s0=0.f,s1=0.f,s2=0.f,s3=0.f;
    #pragma unroll
    for (int k = 0; k < L; k += 4) {
        s0 = fmaf(a[k  ], v[k  ], s0);
        s1 = fmaf(a[k+1], v[k+1], s1);
        s2 = fmaf(a[k+2], v[k+2], s2);
        s3 = fmaf(a[k+3], v[k+3], s3);
    }
    return (s0+s1)+(s2+s3);
}

__device__ __forceinline__ float blkred(float r, volatile float* buf2, int tid){
    #pragma unroll
    for (int m = 16; m; m >>= 1) r += __shfl_xor_sync(0xffffffffu, r, m);
    __syncthreads();
    if ((tid & 31) == 0) buf2[tid >> 5] = r;
    __syncthreads();
    return buf2[0] + buf2[1];
}

__global__ __launch_bounds__(64) void zca_eigen(const float* __restrict__ v_init,
                                               const float* __restrict__ weight,
                                               const float* __restrict__ bias)
{
    const int g = blockIdx.x, i = threadIdx.x;
    __shared__ float vb[2][L];
    __shared__ float red2[2];

    float a[L], S[L];
    #pragma unroll
    for (int k = 0; k < L; ++k) { a[k] = g_cov[(size_t)g*L*L + i*L + k]; S[k] = 0.f; }

    float lam_prev = 0.f;

    for (int j = 0; j < L; ++j) {
        vb[0][i] = v_init[(size_t)(g*L + j)*L + i];
        __syncthreads();
        int p = 0;
        float w = 0.f;
        #pragma unroll 1
        for (int it = 0; it < NPI; ++it) {
            w = dot64(a, vb[p]);
            vb[p^1][i] = w;
            __syncthreads();
            p ^= 1;
        }
        const float n2  = blkred(w*w, red2, i);
        const float vh  = w * (1.0f / (sqrtf(n2) + 1e-12f));
        vb[p^1][i] = vh;
        __syncthreads();
        const float* cv = vb[p^1];
        const float av  = dot64(a, cv);
        const float num = blkred(vh*av, red2, i);
        const float den = blkred(vh*vh, red2, i);
        const float lam = num / den;
        if (j > 0 && (lam_prev < lam || lam < EPSV)) break;
        const float c1 = rsqrtf(lam) * vh;   // S += rsqrt(lam) * v v^T (row factor vh!)
        #pragma unroll
        for (int k = 0; k < L; ++k) {
            const float t = cv[k];
            S[k] = fmaf(c1, t, S[k]);
            a[k] = fmaf(-av, t, a[k]);
        }
        lam_prev = lam;
        __syncthreads();
    }

    const int c = g*L + i;
    const float wgt = weight[c];
    float dm = 0.f;
    #pragma unroll
    for (int k = 0; k < L; ++k) dm = fmaf(S[k], g_mu[g*L + k], dm);
    g_off[c] = bias[c] - wgt*dm;
    #pragma unroll
    for (int k = 0; k < L; ++k) g_R[(size_t)c*L + k] = wgt * S[k];
}

// =====================================================================
// Kernel 4 (NEW): whiten + affine, out = R x + off.
// grid (49, 16, 8), 64 threads = 2 warps; each warp owns one n-batch's
// 64x64 tile (R^T shared). Per thread: 8 rows x 16 cols, addressed so
// every LDS.128 is a conflict-free single wavefront:
//   rows: {ti*4..+3} u {32+ti*4..+3}  (A loads: 8 consecutive lines)
//   cols: q*16 + tj*4 + {0..3}, q=0..3 (B loads: 4 consecutive lines, bcast)
// Per k: 6 LDS.128 : 64 FFMA2.  smem = 16KB R^T + 2x16KB tiles = 48KB.
// =====================================================================
__global__ __launch_bounds__(64) void zca_whiten(const float* __restrict__ x,
                                                 float* __restrict__ out)
{
    const int bx = blockIdx.x, g = blockIdx.z;
    __shared__ float R_sT[L][L];       // [k][i]
    __shared__ float tile[2][L][L];    // [half][k][col]

    const int tid  = threadIdx.x;
    const int half = tid >> 5, t32 = tid & 31;
    const int ti   = t32 >> 2, tj = t32 & 3;
    const int n    = blockIdx.y*2 + half;

    {   // load R transposed: thread 'tid' handles R row tid
        const float* Rrow = &g_R[(size_t)(g*L + tid)*L];
        #pragma unroll
        for (int q = 0; q < 16; ++q) {
            const float4 rv = *(const float4*)&Rrow[4*q];
            R_sT[4*q+0][tid] = rv.x; R_sT[4*q+1][tid] = rv.y;
            R_sT[4*q+2][tid] = rv.z; R_sT[4*q+3][tid] = rv.w;
        }
    }

    const int colbase = bx * 64;
    const float* xb = x   + ((size_t)n*CCH + (size_t)g*L)*HWSZ + colbase;
    float*       ob = out + ((size_t)n*CCH + (size_t)g*L)*HWSZ + colbase;

    // each warp fills its own 64x64 tile (coalesced, 2 threads per row)
    #pragma unroll
    for (int q = 0; q < 32; ++q) {
        const int f4  = q*32 + t32;
        const int row = f4 >> 4, c4 = (f4 & 15)*4;
        *(float4*)&tile[half][row][c4] = *(const float4*)(xb + (size_t)row*HWSZ + c4);
    }
    __syncthreads();

    ull acc[8][8];   // [r][2q + (0|1)]
    #pragma unroll
    for (int r = 0; r < 8; ++r)
        #pragma unroll
        for (int c = 0; c < 8; ++c) acc[r][c] = 0ull;

    #pragma unroll 4
    for (int k = 0; k < L; ++k) {
        const float4 Alo = *(const float4*)&R_sT[k][ti*4];
        const float4 Ahi = *(const float4*)&R_sT[k][32 + ti*4];
        float4 B[4];
        #pragma unroll
        for (int q = 0; q < 4; ++q)
            B[q] = *(const float4*)&tile[half][k][q*16 + tj*4];
        ull ar[8];
        ar[0]=pack2(Alo.x,Alo.x); ar[1]=pack2(Alo.y,Alo.y);
        ar[2]=pack2(Alo.z,Alo.z); ar[3]=pack2(Alo.w,Alo.w);
        ar[4]=pack2(Ahi.x,Ahi.x); ar[5]=pack2(Ahi.y,Ahi.y);
        ar[6]=pack2(Ahi.z,Ahi.z); ar[7]=pack2(Ahi.w,Ahi.w);
        #pragma unroll
        for (int q = 0; q < 4; ++q) {
            const ull b0 = pack2(B[q].x, B[q].y), b1 = pack2(B[q].z, B[q].w);
            #pragma unroll
            for (int r = 0; r < 8; ++r) {
                fma2(acc[r][2*q  ], ar[r], b0);
                fma2(acc[r][2*q+1], ar[r], b1);
            }
        }
    }

    #pragma unroll
    for (int r = 0; r < 8; ++r) {
        const int row = (r < 4) ? (ti*4 + r) : (32 + ti*4 + (r - 4));
        const float o = g_off[g*L + row];
        #pragma unroll
        for (int q = 0; q < 4; ++q) {
            const float2 u = unpk(acc[r][2*q]), v = unpk(acc[r][2*q+1]);
            float4 w; w.x = u.x+o; w.y = u.y+o; w.z = v.x+o; w.w = v.y+o;
            *(float4*)(ob + (size_t)row*HWSZ + q*16 + tj*4) = w;
        }
    }
}

// =====================================================================
extern "C" void kernel_launch(void* const* d_in, const int* in_sizes, int n_in,
                              void* d_out, int out_size)
{
    const float* x      = (const float*)d_in[0];
    const float* v_init = (const float*)d_in[1];
    const float* weight = (const float*)d_in[2];
    const float* bias   = (const float*)d_in[3];
    float* out = (float*)d_out;
    (void)in_sizes; (void)n_in; (void)out_size;

    zca_gram    <<<dim3(SPLITS, NB, G), 64>>>(x);
    zca_finalize<<<dim3(4, G), 256>>>();
    zca_eigen   <<<G, 64>>>(v_init, weight, bias);
    zca_whiten  <<<dim3(49, NB/2, G), 64>>>(x, out);
}

// round 11
// speedup vs baseline: 1.1855x; 1.0449x over previous
#include <cuda_runtime.h>

#define G      8
#define L      64
#define CCH    512
#define NB     32
#define HWSZ   3136
#define MTOT   (NB*HWSZ)
#define EPSV   1e-4f
#define NPI    19
#define SPLITS 2
#define SCOLS  (HWSZ/SPLITS)   // 1568
#define NCHK   (NB*SPLITS)     // 64 partial chunks per group
#define TT     32

// ---------------- static scratch ----------------
__device__ float g_pg  [(size_t)G*NCHK*L*L];   // 8.4 MB
__device__ float g_psum[(size_t)G*NCHK*L];
__device__ float g_cov [(size_t)G*L*L];
__device__ float g_mu  [CCH];
__device__ float g_R   [(size_t)CCH*L];
__device__ float g_off [CCH];

// ---------------- packed f32x2 helpers ----------------
typedef unsigned long long ull;
__device__ __forceinline__ ull pack2(float lo, float hi){
    ull r; asm("mov.b64 %0,{%1,%2};" : "=l"(r) : "f"(lo), "f"(hi)); return r;
}
__device__ __forceinline__ void fma2(ull& d, ull a, ull b){
    asm("fma.rn.f32x2 %0,%1,%2,%0;" : "+l"(d) : "l"(a), "l"(b));
}
__device__ __forceinline__ float2 unpk(ull v){
    float a, b; asm("mov.b64 {%0,%1},%2;" : "=f"(a), "=f"(b) : "l"(v));
    return make_float2(a, b);
}

// =====================================================================
// Kernel 1: fused channel-sum + Gram partials. (byte-identical to R10)
// =====================================================================
__global__ __launch_bounds__(64) void zca_gram(const float* __restrict__ x)
{
    const int g = blockIdx.z, n = blockIdx.y, sp = blockIdx.x;
    const float* xb = x + ((size_t)n*CCH + (size_t)g*L)*HWSZ + (size_t)sp*SCOLS;

    __shared__ float tileT[TT][L+4];   // [col][row], stride 68 (16B-aligned rows)
    __shared__ float outb[L*L];
    __shared__ float rs_s[L][8];

    const int tid = threadIdx.x;
    const int ti  = tid >> 3, tj = tid & 7;
    const int i0  = ti*8,     j0 = tj*8;

    ull acc[4][8];
    #pragma unroll
    for (int r = 0; r < 4; ++r)
        #pragma unroll
        for (int c = 0; c < 8; ++c) acc[r][c] = 0ull;
    float rsum[8] = {0.f,0.f,0.f,0.f,0.f,0.f,0.f,0.f};

    for (int s = 0; s < SCOLS; s += TT) {
        __syncthreads();   // WAR on tileT
        #pragma unroll
        for (int q = 0; q < 8; ++q) {
            const int row = ti + 8*q;
            const float4 v = *(const float4*)(xb + (size_t)row*HWSZ + s + tj*4);
            tileT[tj*4+0][row] = v.x; tileT[tj*4+1][row] = v.y;
            tileT[tj*4+2][row] = v.z; tileT[tj*4+3][row] = v.w;
            rsum[q] += (v.x + v.y) + (v.z + v.w);
        }
        __syncthreads();

        #pragma unroll 8
        for (int cc = 0; cc < TT; ++cc) {
            ull a2[4];
            #pragma unroll
            for (int r = 0; r < 4; ++r) a2[r] = *(const ull*)&tileT[cc][i0 + 2*r];
            const float4 B1 = *(const float4*)&tileT[cc][j0];
            const float4 B2 = *(const float4*)&tileT[cc][j0+4];
            ull bp[8];
            bp[0]=pack2(B1.x,B1.x); bp[1]=pack2(B1.y,B1.y);
            bp[2]=pack2(B1.z,B1.z); bp[3]=pack2(B1.w,B1.w);
            bp[4]=pack2(B2.x,B2.x); bp[5]=pack2(B2.y,B2.y);
            bp[6]=pack2(B2.z,B2.z); bp[7]=pack2(B2.w,B2.w);
            #pragma unroll
            for (int r = 0; r < 4; ++r)
                #pragma unroll
                for (int c = 0; c < 8; ++c) fma2(acc[r][c], a2[r], bp[c]);
        }
    }

    #pragma unroll
    for (int r = 0; r < 4; ++r)
        #pragma unroll
        for (int c = 0; c < 8; ++c) {
            const float2 f = unpk(acc[r][c]);
            outb[(i0+2*r  )*L + j0 + c] = f.x;
            outb[(i0+2*r+1)*L + j0 + c] = f.y;
        }
    #pragma unroll
    for (int q = 0; q < 8; ++q) rs_s[ti + 8*q][tj] = rsum[q];
    __syncthreads();

    const int ch = n*SPLITS + sp;
    float* pg = g_pg + (size_t)(g*NCHK + ch)*L*L;
    #pragma unroll
    for (int q = 0; q < 16; ++q)
        *(float4*)&pg[(tid + 64*q)*4] = *(const float4*)&outb[(tid + 64*q)*4];
    {
        float ssum = 0.f;
        #pragma unroll
        for (int q = 0; q < 8; ++q) ssum += rs_s[tid][q];
        g_psum[(g*NCHK + ch)*L + tid] = ssum;
    }
}

// =====================================================================
// Kernel 2: reduce partials -> mu, cov. (byte-identical to R10)
// =====================================================================
__global__ __launch_bounds__(256) void zca_finalize()
{
    const int part = blockIdx.x, g = blockIdx.y, tid = threadIdx.x;
    __shared__ float mu_s[L];
    if (tid < L) {
        float s0=0.f,s1=0.f,s2=0.f,s3=0.f;
        for (int ch = 0; ch < NCHK; ch += 4) {
            s0 += g_psum[(g*NCHK + ch  )*L + tid];
            s1 += g_psum[(g*NCHK + ch+1)*L + tid];
            s2 += g_psum[(g*NCHK + ch+2)*L + tid];
            s3 += g_psum[(g*NCHK + ch+3)*L + tid];
        }
        const float m = ((s0+s1)+(s2+s3)) / (float)MTOT;
        mu_s[tid] = m;
        if (part == 0) g_mu[g*L + tid] = m;
    }
    __syncthreads();
    const int base = part*1024;
    float acc[4] = {0.f,0.f,0.f,0.f};
    for (int ch = 0; ch < NCHK; ++ch) {
        const float* p = g_pg + (size_t)(g*NCHK + ch)*L*L + base;
        #pragma unroll
        for (int e = 0; e < 4; ++e) acc[e] += p[tid + e*256];
    }
    #pragma unroll
    for (int e = 0; e < 4; ++e) {
        const int idx = base + tid + e*256, i = idx >> 6, j = idx & 63;
        float c = acc[e] / (float)MTOT - mu_s[i]*mu_s[j];
        if (i == j) c += EPSV;
        g_cov[g*L*L + idx] = c;
    }
}

// =====================================================================
// Kernel 3: eigen. (byte-identical to R10, incl. c1 = rsqrtf(lam)*vh)
// =====================================================================
__device__ __forceinline__ float dot64(const float* a, const float* v){
    float s0=0.f,s1=0.f,s2=0.f,s3=0.f;
    #pragma unroll
    for (int k = 0; k < L; k += 4) {
        s0 = fmaf(a[k  ], v[k  ], s0);
        s1 = fmaf(a[k+1], v[k+1], s1);
        s2 = fmaf(a[k+2], v[k+2], s2);
        s3 = fmaf(a[k+3], v[k+3], s3);
    }
    return (s0+s1)+(s2+s3);
}

__device__ __forceinline__ float blkred(float r, volatile float* buf2, int tid){
    #pragma unroll
    for (int m = 16; m; m >>= 1) r += __shfl_xor_sync(0xffffffffu, r, m);
    __syncthreads();
    if ((tid & 31) == 0) buf2[tid >> 5] = r;
    __syncthreads();
    return buf2[0] + buf2[1];
}

__global__ __launch_bounds__(64) void zca_eigen(const float* __restrict__ v_init,
                                               const float* __restrict__ weight,
                                               const float* __restrict__ bias)
{
    const int g = blockIdx.x, i = threadIdx.x;
    __shared__ float vb[2][L];
    __shared__ float red2[2];

    float a[L], S[L];
    #pragma unroll
    for (int k = 0; k < L; ++k) { a[k] = g_cov[(size_t)g*L*L + i*L + k]; S[k] = 0.f; }

    float lam_prev = 0.f;

    for (int j = 0; j < L; ++j) {
        vb[0][i] = v_init[(size_t)(g*L + j)*L + i];
        __syncthreads();
        int p = 0;
        float w = 0.f;
        #pragma unroll 1
        for (int it = 0; it < NPI; ++it) {
            w = dot64(a, vb[p]);
            vb[p^1][i] = w;
            __syncthreads();
            p ^= 1;
        }
        const float n2  = blkred(w*w, red2, i);
        const float vh  = w * (1.0f / (sqrtf(n2) + 1e-12f));
        vb[p^1][i] = vh;
        __syncthreads();
        const float* cv = vb[p^1];
        const float av  = dot64(a, cv);
        const float num = blkred(vh*av, red2, i);
        const float den = blkred(vh*vh, red2, i);
        const float lam = num / den;
        if (j > 0 && (lam_prev < lam || lam < EPSV)) break;
        const float c1 = rsqrtf(lam) * vh;   // S += rsqrt(lam) * v v^T (row factor vh!)
        #pragma unroll
        for (int k = 0; k < L; ++k) {
            const float t = cv[k];
            S[k] = fmaf(c1, t, S[k]);
            a[k] = fmaf(-av, t, a[k]);
        }
        lam_prev = lam;
        __syncthreads();
    }

    const int c = g*L + i;
    const float wgt = weight[c];
    float dm = 0.f;
    #pragma unroll
    for (int k = 0; k < L; ++k) dm = fmaf(S[k], g_mu[g*L + k], dm);
    g_off[c] = bias[c] - wgt*dm;
    #pragma unroll
    for (int k = 0; k < L; ++k) g_R[(size_t)c*L + k] = wgt * S[k];
}

// =====================================================================
// Kernel 4 (NEW): whiten + affine, out = R x + off.
// grid (49, 16, 8), 128 threads = 4 warps; halves own n-batches, share R^T.
// Per thread 8x8 tile with split addressing so every LDS.128 is one
// conflict-free wavefront:
//   rows: {ti*4..+3} u {32+ti*4..+3}   (A: 4 lines, 8-way bcast)
//   cols: {tj*4..+3} u {32+tj*4..+3}   (B: 8 lines, 4-way bcast)
// Per k per thread: 4 LDS.128 : 32 FFMA2. 16 warps/SM (4 blocks x 48KB).
// =====================================================================
__global__ __launch_bounds__(128, 4) void zca_whiten(const float* __restrict__ x,
                                                     float* __restrict__ out)
{
    const int bx = blockIdx.x, g = blockIdx.z;
    __shared__ float R_sT[L][L];       // [k][i]
    __shared__ float tile[2][L][L];    // [half][k][col]

    const int tid  = threadIdx.x;
    const int half = tid >> 6, t64 = tid & 63;
    const int ti   = t64 >> 3, tj = t64 & 7;
    const int n    = blockIdx.y*2 + half;

    {   // load R transposed: thread pair per R row
        const int row = tid >> 1, kh = (tid & 1)*32;
        #pragma unroll
        for (int q = 0; q < 8; ++q) {
            const float4 rv = *(const float4*)&g_R[(size_t)(g*L + row)*L + kh + 4*q];
            R_sT[kh+4*q+0][row] = rv.x; R_sT[kh+4*q+1][row] = rv.y;
            R_sT[kh+4*q+2][row] = rv.z; R_sT[kh+4*q+3][row] = rv.w;
        }
    }

    const int colbase = bx * 64;
    const float* xb = x   + ((size_t)n*CCH + (size_t)g*L)*HWSZ + colbase;
    float*       ob = out + ((size_t)n*CCH + (size_t)g*L)*HWSZ + colbase;

    // each half (64 threads) fills its own 64x64 tile, coalesced
    #pragma unroll
    for (int q = 0; q < 16; ++q) {
        const int f4  = q*64 + t64;
        const int row = f4 >> 4, c4 = (f4 & 15)*4;
        *(float4*)&tile[half][row][c4] = *(const float4*)(xb + (size_t)row*HWSZ + c4);
    }
    __syncthreads();

    ull acc[8][4];   // [r][ lo-pair0, lo-pair1, hi-pair0, hi-pair1 ]
    #pragma unroll
    for (int r = 0; r < 8; ++r)
        #pragma unroll
        for (int c = 0; c < 4; ++c) acc[r][c] = 0ull;

    #pragma unroll 4
    for (int k = 0; k < L; ++k) {
        const float4 Alo = *(const float4*)&R_sT[k][ti*4];
        const float4 Ahi = *(const float4*)&R_sT[k][32 + ti*4];
        const float4 Blo = *(const float4*)&tile[half][k][tj*4];
        const float4 Bhi = *(const float4*)&tile[half][k][32 + tj*4];
        const ull b0 = pack2(Blo.x,Blo.y), b1 = pack2(Blo.z,Blo.w);
        const ull b2 = pack2(Bhi.x,Bhi.y), b3 = pack2(Bhi.z,Bhi.w);
        ull ar[8];
        ar[0]=pack2(Alo.x,Alo.x); ar[1]=pack2(Alo.y,Alo.y);
        ar[2]=pack2(Alo.z,Alo.z); ar[3]=pack2(Alo.w,Alo.w);
        ar[4]=pack2(Ahi.x,Ahi.x); ar[5]=pack2(Ahi.y,Ahi.y);
        ar[6]=pack2(Ahi.z,Ahi.z); ar[7]=pack2(Ahi.w,Ahi.w);
        #pragma unroll
        for (int r = 0; r < 8; ++r) {
            fma2(acc[r][0], ar[r], b0); fma2(acc[r][1], ar[r], b1);
            fma2(acc[r][2], ar[r], b2); fma2(acc[r][3], ar[r], b3);
        }
    }

    #pragma unroll
    for (int r = 0; r < 8; ++r) {
        const int row = (r < 4) ? (ti*4 + r) : (32 + ti*4 + (r - 4));
        const float o = g_off[g*L + row];
        const float2 u0=unpk(acc[r][0]), u1=unpk(acc[r][1]);
        const float2 u2=unpk(acc[r][2]), u3=unpk(acc[r][3]);
        float4 w0, w1;
        w0.x=u0.x+o; w0.y=u0.y+o; w0.z=u1.x+o; w0.w=u1.y+o;
        w1.x=u2.x+o; w1.y=u2.y+o; w1.z=u3.x+o; w1.w=u3.y+o;
        *(float4*)(ob + (size_t)row*HWSZ + tj*4     ) = w0;
        *(float4*)(ob + (size_t)row*HWSZ + 32 + tj*4) = w1;
    }
}

// =====================================================================
extern "C" void kernel_launch(void* const* d_in, const int* in_sizes, int n_in,
                              void* d_out, int out_size)
{
    const float* x      = (const float*)d_in[0];
    const float* v_init = (const float*)d_in[1];
    const float* weight = (const float*)d_in[2];
    const float* bias   = (const float*)d_in[3];
    float* out = (float*)d_out;
    (void)in_sizes; (void)n_in; (void)out_size;

    zca_gram    <<<dim3(SPLITS, NB, G), 64>>>(x);
    zca_finalize<<<dim3(4, G), 256>>>();
    zca_eigen   <<<G, 64>>>(v_init, weight, bias);
    zca_whiten  <<<dim3(49, NB/2, G), 128>>>(x, out);
}

// round 13
// speedup vs baseline: 1.2392x; 1.0453x over previous
#include <cuda_runtime.h>

#define G      8
#define L      64
#define CCH    512
#define NB     32
#define HWSZ   3136
#define MTOT   (NB*HWSZ)
#define EPSV   1e-4f
#define NPI    19
#define SPLITS 2
#define SCOLS  (HWSZ/SPLITS)   // 1568
#define NCHK   (NB*SPLITS)     // 64 partial chunks per group
#define TT     32

// ---------------- static scratch ----------------
__device__ float g_pg  [(size_t)G*NCHK*L*L];   // 8.4 MB
__device__ float g_psum[(size_t)G*NCHK*L];
__device__ float g_cov [(size_t)G*L*L];
__device__ float g_mu  [CCH];
__device__ float g_R   [(size_t)CCH*L];
__device__ float g_off [CCH];

// ---------------- packed f32x2 helpers ----------------
typedef unsigned long long ull;
__device__ __forceinline__ ull pack2(float lo, float hi){
    ull r; asm("mov.b64 %0,{%1,%2};" : "=l"(r) : "f"(lo), "f"(hi)); return r;
}
__device__ __forceinline__ void fma2(ull& d, ull a, ull b){
    asm("fma.rn.f32x2 %0,%1,%2,%0;" : "+l"(d) : "l"(a), "l"(b));
}
__device__ __forceinline__ float2 unpk(ull v){
    float a, b; asm("mov.b64 {%0,%1},%2;" : "=f"(a), "=f"(b) : "l"(v));
    return make_float2(a, b);
}

// =====================================================================
// Kernel 1: fused channel-sum + Gram partials.
// NOW 128 threads (4 warps -> all 4 SMSPs). Same grid (SPLITS, NB, G).
// Per-thread tile: 4 row-pairs x 4 cols. Per-element FMA chains (one
// f32x2 lane, cc ascending per tile, s ascending) and rsum partial
// sequences are bit-identical to the R11 passing run — only the
// thread->element mapping changed.
// =====================================================================
__global__ __launch_bounds__(128) void zca_gram(const float* __restrict__ x)
{
    const int g = blockIdx.z, n = blockIdx.y, sp = blockIdx.x;
    const float* xb = x + ((size_t)n*CCH + (size_t)g*L)*HWSZ + (size_t)sp*SCOLS;

    __shared__ float tileT[TT][L+4];   // [col][row], stride 68 (16B-aligned rows)
    __shared__ float outb[L*L];
    __shared__ float rs_s[L][8];

    const int tid  = threadIdx.x;
    const int ti   = tid >> 4, tj = tid & 15;   // compute map: 8 x 16
    const int i0   = ti*8,     j0 = tj*4;
    const int lrow = tid >> 3, lch = tid & 7;   // loader map: 16 rows x 8 chunks

    ull acc[4][4];
    #pragma unroll
    for (int r = 0; r < 4; ++r)
        #pragma unroll
        for (int c = 0; c < 4; ++c) acc[r][c] = 0ull;
    float rsum[4] = {0.f,0.f,0.f,0.f};

    for (int s = 0; s < SCOLS; s += TT) {
        __syncthreads();   // WAR on tileT
        #pragma unroll
        for (int q = 0; q < 4; ++q) {
            const int row = lrow + 16*q;
            const float4 v = *(const float4*)(xb + (size_t)row*HWSZ + s + lch*4);
            tileT[lch*4+0][row] = v.x; tileT[lch*4+1][row] = v.y;
            tileT[lch*4+2][row] = v.z; tileT[lch*4+3][row] = v.w;
            rsum[q] += (v.x + v.y) + (v.z + v.w);
        }
        __syncthreads();

        #pragma unroll 8
        for (int cc = 0; cc < TT; ++cc) {
            ull a2[4];
            #pragma unroll
            for (int r = 0; r < 4; ++r) a2[r] = *(const ull*)&tileT[cc][i0 + 2*r];
            const float4 B = *(const float4*)&tileT[cc][j0];
            ull bp[4];
            bp[0]=pack2(B.x,B.x); bp[1]=pack2(B.y,B.y);
            bp[2]=pack2(B.z,B.z); bp[3]=pack2(B.w,B.w);
            #pragma unroll
            for (int r = 0; r < 4; ++r)
                #pragma unroll
                for (int c = 0; c < 4; ++c) fma2(acc[r][c], a2[r], bp[c]);
        }
    }

    // stage results in smem, then coalesced writes
    #pragma unroll
    for (int r = 0; r < 4; ++r)
        #pragma unroll
        for (int c = 0; c < 4; ++c) {
            const float2 f = unpk(acc[r][c]);
            outb[(i0+2*r  )*L + j0 + c] = f.x;
            outb[(i0+2*r+1)*L + j0 + c] = f.y;
        }
    #pragma unroll
    for (int q = 0; q < 4; ++q) rs_s[lrow + 16*q][lch] = rsum[q];
    __syncthreads();

    const int ch = n*SPLITS + sp;
    float* pg = g_pg + (size_t)(g*NCHK + ch)*L*L;
    #pragma unroll
    for (int q = 0; q < 8; ++q)
        *(float4*)&pg[(tid + 128*q)*4] = *(const float4*)&outb[(tid + 128*q)*4];
    if (tid < L) {
        float ssum = 0.f;
        #pragma unroll
        for (int q = 0; q < 8; ++q) ssum += rs_s[tid][q];
        g_psum[(g*NCHK + ch)*L + tid] = ssum;
    }
}

// =====================================================================
// Kernel 2: reduce partials -> mu, cov. (byte-identical to R11)
// =====================================================================
__global__ __launch_bounds__(256) void zca_finalize()
{
    const int part = blockIdx.x, g = blockIdx.y, tid = threadIdx.x;
    __shared__ float mu_s[L];
    if (tid < L) {
        float s0=0.f,s1=0.f,s2=0.f,s3=0.f;
        for (int ch = 0; ch < NCHK; ch += 4) {
            s0 += g_psum[(g*NCHK + ch  )*L + tid];
            s1 += g_psum[(g*NCHK + ch+1)*L + tid];
            s2 += g_psum[(g*NCHK + ch+2)*L + tid];
            s3 += g_psum[(g*NCHK + ch+3)*L + tid];
        }
        const float m = ((s0+s1)+(s2+s3)) / (float)MTOT;
        mu_s[tid] = m;
        if (part == 0) g_mu[g*L + tid] = m;
    }
    __syncthreads();
    const int base = part*1024;
    float acc[4] = {0.f,0.f,0.f,0.f};
    for (int ch = 0; ch < NCHK; ++ch) {
        const float* p = g_pg + (size_t)(g*NCHK + ch)*L*L + base;
        #pragma unroll
        for (int e = 0; e < 4; ++e) acc[e] += p[tid + e*256];
    }
    #pragma unroll
    for (int e = 0; e < 4; ++e) {
        const int idx = base + tid + e*256, i = idx >> 6, j = idx & 63;
        float c = acc[e] / (float)MTOT - mu_s[i]*mu_s[j];
        if (i == j) c += EPSV;
        g_cov[g*L*L + idx] = c;
    }
}

// =====================================================================
// Kernel 3: eigen — f32x2-packed, LANE-EXACT vs the scalar dot64:
// q01 lanes = (s0,s1), q23 lanes = (s2,s3); each lane replays the exact
// scalar accumulator sequence (k = j mod 4, ascending); final add is
// (s0+s1)+(s2+s3). Deflation updates packed per-lane-identical.
// =====================================================================
__device__ __forceinline__ float dotp2(const ull* a2, const float* v){
    ull q01 = 0ull, q23 = 0ull;
    #pragma unroll
    for (int k = 0; k < L; k += 4) {
        const float4 vv = *(const float4*)&v[k];
        fma2(q01, a2[k/2  ], pack2(vv.x, vv.y));
        fma2(q23, a2[k/2+1], pack2(vv.z, vv.w));
    }
    const float2 f01 = unpk(q01), f23 = unpk(q23);
    return (f01.x + f01.y) + (f23.x + f23.y);
}

__device__ __forceinline__ float blkred(float r, volatile float* buf2, int tid){
    #pragma unroll
    for (int m = 16; m; m >>= 1) r += __shfl_xor_sync(0xffffffffu, r, m);
    __syncthreads();
    if ((tid & 31) == 0) buf2[tid >> 5] = r;
    __syncthreads();
    return buf2[0] + buf2[1];
}

__global__ __launch_bounds__(64) void zca_eigen(const float* __restrict__ v_init,
                                               const float* __restrict__ weight,
                                               const float* __restrict__ bias)
{
    const int g = blockIdx.x, i = threadIdx.x;
    __shared__ float vb[2][L];
    __shared__ float red2[2];

    ull a2[32], s2[32];
    #pragma unroll
    for (int k2 = 0; k2 < 32; ++k2) {
        const float2 c = *(const float2*)&g_cov[(size_t)g*L*L + i*L + 2*k2];
        a2[k2] = pack2(c.x, c.y);
        s2[k2] = 0ull;
    }

    float lam_prev = 0.f;

    for (int j = 0; j < L; ++j) {
        vb[0][i] = v_init[(size_t)(g*L + j)*L + i];
        __syncthreads();
        int p = 0;
        float w = 0.f;
        #pragma unroll 1
        for (int it = 0; it < NPI; ++it) {
            w = dotp2(a2, vb[p]);
            vb[p^1][i] = w;
            __syncthreads();
            p ^= 1;
        }
        const float n2  = blkred(w*w, red2, i);
        const float vh  = w * (1.0f / (sqrtf(n2) + 1e-12f));
        vb[p^1][i] = vh;
        __syncthreads();
        const float* cv = vb[p^1];
        const float av  = dotp2(a2, cv);
        const float num = blkred(vh*av, red2, i);
        const float den = blkred(vh*vh, red2, i);
        const float lam = num / den;
        if (j > 0 && (lam_prev < lam || lam < EPSV)) break;
        const float c1 = rsqrtf(lam) * vh;   // S += rsqrt(lam) * v v^T (row factor vh!)
        const ull c1p = pack2(c1, c1);
        const ull avn = pack2(-av, -av);
        #pragma unroll
        for (int k2 = 0; k2 < 32; ++k2) {
            const ull vp = *(const ull*)&cv[2*k2];
            fma2(s2[k2], c1p, vp);     // lane: S[k] = fmaf(c1,  t, S[k])
            fma2(a2[k2], avn, vp);     // lane: a[k] = fmaf(-av, t, a[k])
        }
        lam_prev = lam;
        __syncthreads();
    }

    // fold affine: R = diag(w) S, off = bias - R mu
    float S[L];
    #pragma unroll
    for (int k2 = 0; k2 < 32; ++k2) {
        const float2 f = unpk(s2[k2]);
        S[2*k2] = f.x; S[2*k2+1] = f.y;
    }
    const int c = g*L + i;
    const float wgt = weight[c];
    float dm = 0.f;
    #pragma unroll
    for (int k = 0; k < L; ++k) dm = fmaf(S[k], g_mu[g*L + k], dm);
    g_off[c] = bias[c] - wgt*dm;
    #pragma unroll
    for (int k = 0; k < L; ++k) g_R[(size_t)c*L + k] = wgt * S[k];
}

// =====================================================================
// Kernel 4: whiten + affine. (byte-identical to R11)
// =====================================================================
__global__ __launch_bounds__(128, 4) void zca_whiten(const float* __restrict__ x,
                                                     float* __restrict__ out)
{
    const int bx = blockIdx.x, g = blockIdx.z;
    __shared__ float R_sT[L][L];       // [k][i]
    __shared__ float tile[2][L][L];    // [half][k][col]

    const int tid  = threadIdx.x;
    const int half = tid >> 6, t64 = tid & 63;
    const int ti   = t64 >> 3, tj = t64 & 7;
    const int n    = blockIdx.y*2 + half;

    {   // load R transposed: thread pair per R row
        const int row = tid >> 1, kh = (tid & 1)*32;
        #pragma unroll
        for (int q = 0; q < 8; ++q) {
            const float4 rv = *(const float4*)&g_R[(size_t)(g*L + row)*L + kh + 4*q];
            R_sT[kh+4*q+0][row] = rv.x; R_sT[kh+4*q+1][row] = rv.y;
            R_sT[kh+4*q+2][row] = rv.z; R_sT[kh+4*q+3][row] = rv.w;
        }
    }

    const int colbase = bx * 64;
    const float* xb = x   + ((size_t)n*CCH + (size_t)g*L)*HWSZ + colbase;
    float*       ob = out + ((size_t)n*CCH + (size_t)g*L)*HWSZ + colbase;

    #pragma unroll
    for (int q = 0; q < 16; ++q) {
        const int f4  = q*64 + t64;
        const int row = f4 >> 4, c4 = (f4 & 15)*4;
        *(float4*)&tile[half][row][c4] = *(const float4*)(xb + (size_t)row*HWSZ + c4);
    }
    __syncthreads();

    ull acc[8][4];
    #pragma unroll
    for (int r = 0; r < 8; ++r)
        #pragma unroll
        for (int c = 0; c < 4; ++c) acc[r][c] = 0ull;

    #pragma unroll 4
    for (int k = 0; k < L; ++k) {
        const float4 Alo = *(const float4*)&R_sT[k][ti*4];
        const float4 Ahi = *(const float4*)&R_sT[k][32 + ti*4];
        const float4 Blo = *(const float4*)&tile[half][k][tj*4];
        const float4 Bhi = *(const float4*)&tile[half][k][32 + tj*4];
        const ull b0 = pack2(Blo.x,Blo.y), b1 = pack2(Blo.z,Blo.w);
        const ull b2 = pack2(Bhi.x,Bhi.y), b3 = pack2(Bhi.z,Bhi.w);
        ull ar[8];
        ar[0]=pack2(Alo.x,Alo.x); ar[1]=pack2(Alo.y,Alo.y);
        ar[2]=pack2(Alo.z,Alo.z); ar[3]=pack2(Alo.w,Alo.w);
        ar[4]=pack2(Ahi.x,Ahi.x); ar[5]=pack2(Ahi.y,Ahi.y);
        ar[6]=pack2(Ahi.z,Ahi.z); ar[7]=pack2(Ahi.w,Ahi.w);
        #pragma unroll
        for (int r = 0; r < 8; ++r) {
            fma2(acc[r][0], ar[r], b0); fma2(acc[r][1], ar[r], b1);
            fma2(acc[r][2], ar[r], b2); fma2(acc[r][3], ar[r], b3);
        }
    }

    #pragma unroll
    for (int r = 0; r < 8; ++r) {
        const int row = (r < 4) ? (ti*4 + r) : (32 + ti*4 + (r - 4));
        const float o = g_off[g*L + row];
        const float2 u0=unpk(acc[r][0]), u1=unpk(acc[r][1]);
        const float2 u2=unpk(acc[r][2]), u3=unpk(acc[r][3]);
        float4 w0, w1;
        w0.x=u0.x+o; w0.y=u0.y+o; w0.z=u1.x+o; w0.w=u1.y+o;
        w1.x=u2.x+o; w1.y=u2.y+o; w1.z=u3.x+o; w1.w=u3.y+o;
        *(float4*)(ob + (size_t)row*HWSZ + tj*4     ) = w0;
        *(float4*)(ob + (size_t)row*HWSZ + 32 + tj*4) = w1;
    }
}

// =====================================================================
extern "C" void kernel_launch(void* const* d_in, const int* in_sizes, int n_in,
                              void* d_out, int out_size)
{
    const float* x      = (const float*)d_in[0];
    const float* v_init = (const float*)d_in[1];
    const float* weight = (const float*)d_in[2];
    const float* bias   = (const float*)d_in[3];
    float* out = (float*)d_out;
    (void)in_sizes; (void)n_in; (void)out_size;

    zca_gram    <<<dim3(SPLITS, NB, G), 128>>>(x);
    zca_finalize<<<dim3(4, G), 256>>>();
    zca_eigen   <<<G, 64>>>(v_init, weight, bias);
    zca_whiten  <<<dim3(49, NB/2, G), 128>>>(x, out);
}